// round 10
// baseline (speedup 1.0000x reference)
#include <cuda_runtime.h>

// Problem constants (match reference setup_inputs exactly)
#define CANVAS   512
#define CELLS    (CANVAS * CANVAS)   // 262144
#define BATCH    2
#define NLI      1000000
#define NRA      500000
#define NWORDS   (CELLS / 32)        // 8192 u32 words per batch bitmap

// Scratch: dyn byte table (scatter target) + dilated BIT table per batch.
// g_dyn is zero-initialized at module load; li_kernel re-zeros it at the end
// of every call (after dilate, its last reader), so every kernel_launch call
// -- correctness run and each graph replay -- sees it zeroed. No zero kernel.
__device__ unsigned char g_dyn[BATCH][CELLS];
__device__ unsigned int  g_nbits[BATCH][NWORDS];   // 32 KB per batch

// ---------------------------------------------------------------------------
// 1) Radar pass, 4 points/thread.
//    vr lives at v(5t+1).x, v(5t+2).y, v(5t+3).z, v(5t+4).w (skip first f4).
//    ra_dy positional; ra_ind scattered by idx (STG.128 fast path when the
//    4 idx values are contiguous-positional). dyn marks: racy byte stores.
// ---------------------------------------------------------------------------
__global__ void ra_kernel_v4(const int4*   __restrict__ coords4,  // [B*NRA/2]
                             const float4* __restrict__ in4,      // [B*NRA*5/4]
                             const int4*   __restrict__ idx4,     // [B*NRA/4]
                             float* __restrict__ ra_dy,           // [B*NRA]
                             float* __restrict__ ra_ind)          // [B*NRA]
{
    int t = blockIdx.x * blockDim.x + threadIdx.x;
    if (t >= BATCH * NRA / 4) return;
    int b = t / (NRA / 4);

    float4 v1 = in4[5 * t + 1];
    float4 v2 = in4[5 * t + 2];
    float4 v3 = in4[5 * t + 3];
    float4 v4 = in4[5 * t + 4];
    bool dy0 = fabsf(v1.x) > 0.1f;
    bool dy1 = fabsf(v2.y) > 0.1f;
    bool dy2 = fabsf(v3.z) > 0.1f;
    bool dy3 = fabsf(v4.w) > 0.1f;

    int4 ca = coords4[2 * t];
    int4 cb = coords4[2 * t + 1];
    int f0 = ca.x * CANVAS + ca.y;
    int f1 = ca.z * CANVAS + ca.w;
    int f2 = cb.x * CANVAS + cb.y;
    int f3 = cb.z * CANVAS + cb.w;

    reinterpret_cast<float4*>(ra_dy)[t] =
        make_float4(dy0 ? 1.f : 0.f, dy1 ? 1.f : 0.f,
                    dy2 ? 1.f : 0.f, dy3 ? 1.f : 0.f);

    int4 ix = idx4[t];
    int local0 = 4 * t - b * NRA;
    float* dst = ra_ind + (size_t)b * NRA;
    if (ix.x == local0 && ix.y == local0 + 1 &&
        ix.z == local0 + 2 && ix.w == local0 + 3) {
        *reinterpret_cast<float4*>(dst + local0) =
            make_float4((float)f0, (float)f1, (float)f2, (float)f3);
    } else {
        dst[ix.x] = (float)f0; dst[ix.y] = (float)f1;
        dst[ix.z] = (float)f2; dst[ix.w] = (float)f3;
    }

    unsigned char* dyn = g_dyn[b];
    if (dy0) dyn[f0] = 1;
    if (dy1) dyn[f1] = 1;
    if (dy2) dyn[f2] = 1;
    if (dy3) dyn[f3] = 1;
}

// ---------------------------------------------------------------------------
// 2) Separable 5x5 dilation in byte-SIMD, emitting a BIT-PACKED mask.
//    neigh[sy,sx] = OR_{i,j in [-2,2]} dyn[m(sy+i)][m(sx+j)], with the
//    reference's mod-513 wrap: m(-1)=m(512)=drop, m(-2)=511, m(513)=0.
//    One thread per (b, row, 16-byte segment) [lane == segment]; vertical OR
//    as uint4, horizontal spread via byte funnel-shifts, column-wrap fixups
//    (src col 511 -> out col 0, src col 0 -> out col 511). Bytes stay 0/1,
//    then get packed 4 bytes -> 4 bits; lane pairs merge 16+16 bits via shfl.
// ---------------------------------------------------------------------------
__global__ void dilate_kernel() {
    int t = blockIdx.x * blockDim.x + threadIdx.x;   // exactly 32768 threads
    int b  = t >> 14;            // 512 rows * 32 segs = 16384 per batch
    int rs = t & 16383;
    int sy = rs >> 5;
    int s  = rs & 31;            // 16-byte segment == lane id

    const unsigned char* dyn = g_dyn[b];
    const uint4* dyn4 = reinterpret_cast<const uint4*>(dyn);
    const unsigned int* dynw = reinterpret_cast<const unsigned int*>(dyn);

    unsigned int pw = 0, nw = 0;                  // boundary carry words
    unsigned int c0 = 0, c1 = 0, c2 = 0, c3 = 0;  // vertical OR of segment
    unsigned int vwrap = 0;                       // wrap byte (0/1)

    #pragma unroll
    for (int i = -2; i <= 2; i++) {
        int r = sy + i;
        if (r == -1 || r == 512) continue;        // phantom row -> dropped
        if (r == -2) r = 511;
        else if (r == 513) r = 0;
        int rb4 = r << 5;
        int rbw = r << 7;
        uint4 c = dyn4[rb4 + s];
        c0 |= c.x; c1 |= c.y; c2 |= c.z; c3 |= c.w;
        if (s > 0)  pw |= dynw[rbw + 4 * s - 1];
        if (s < 31) nw |= dynw[rbw + 4 * s + 4];
        if (s == 0)  vwrap |= dyn[(r << 9) + 511];   // src col 511
        if (s == 31) vwrap |= dyn[(r << 9) + 0];     // src col 0
    }

    unsigned int w0 = pw, w1 = c0, w2 = c1, w3 = c2, w4 = c3, w5 = nw;
    unsigned int r0 = w1 | __funnelshift_l(w0, w1, 8) | __funnelshift_l(w0, w1, 16)
                         | __funnelshift_r(w1, w2, 8) | __funnelshift_r(w1, w2, 16);
    unsigned int r1 = w2 | __funnelshift_l(w1, w2, 8) | __funnelshift_l(w1, w2, 16)
                         | __funnelshift_r(w2, w3, 8) | __funnelshift_r(w2, w3, 16);
    unsigned int r2 = w3 | __funnelshift_l(w2, w3, 8) | __funnelshift_l(w2, w3, 16)
                         | __funnelshift_r(w3, w4, 8) | __funnelshift_r(w3, w4, 16);
    unsigned int r3 = w4 | __funnelshift_l(w3, w4, 8) | __funnelshift_l(w3, w4, 16)
                         | __funnelshift_r(w4, w5, 8) | __funnelshift_r(w4, w5, 16);

    if (s == 0)  r0 |= vwrap;         // out col 0   <- src col 511
    if (s == 31) r3 |= vwrap << 24;   // out col 511 <- src col 0

    // pack 16 bytes (each exactly 0/1) -> 16 bits; bit k = col 16*s + k
    unsigned int nib0 = (r0 | (r0 >> 7) | (r0 >> 14) | (r0 >> 21)) & 0xF;
    unsigned int nib1 = (r1 | (r1 >> 7) | (r1 >> 14) | (r1 >> 21)) & 0xF;
    unsigned int nib2 = (r2 | (r2 >> 7) | (r2 >> 14) | (r2 >> 21)) & 0xF;
    unsigned int nib3 = (r3 | (r3 >> 7) | (r3 >> 14) | (r3 >> 21)) & 0xF;
    unsigned int bits16 = nib0 | (nib1 << 4) | (nib2 << 8) | (nib3 << 12);

    // lane pairs (2k, 2k+1) -> one u32 word covering cols 32k..32k+31
    unsigned int hi = __shfl_down_sync(0xFFFFFFFFu, bits16, 1);
    if ((s & 1) == 0)
        g_nbits[b][(sy << 4) + (s >> 1)] = bits16 | (hi << 16);
}

// ---------------------------------------------------------------------------
// 3) Lidar pass, 1024 threads/block, 2 blocks/SM (100% occupancy).
//    148 blocks per batch; each block loads the 32 KB bit table into smem
//    once, strides over point-quads (coalesced LDG.128 in, random LDS bit
//    test, STG.128 out), then helps re-zero g_dyn for the next call.
// ---------------------------------------------------------------------------
__global__ void __launch_bounds__(1024, 2)
li_kernel_smem(const int4* __restrict__ coords4,  // [B*NLI/2]
               const int4* __restrict__ idx4,     // [B*NLI/4]
               float* __restrict__ li_dy,         // [B*NLI]
               float* __restrict__ li_ind)        // [B*NLI]
{
    __shared__ unsigned int sbits[NWORDS];        // 32 KB

    int bpb = gridDim.x / BATCH;                  // blocks per batch (148)
    int b   = blockIdx.x / bpb;
    int blk = blockIdx.x - b * bpb;

    // cooperative load of this batch's bit table (2048 uint4)
    const uint4* src = reinterpret_cast<const uint4*>(g_nbits[b]);
    uint4* dstv = reinterpret_cast<uint4*>(sbits);
    for (int i = threadIdx.x; i < NWORDS / 4; i += blockDim.x)
        dstv[i] = src[i];

    // re-zero g_dyn (dilate was its last reader; restores the entry
    // invariant for the next kernel_launch call). 32768 uint4 total.
    {
        int g = blockIdx.x * blockDim.x + threadIdx.x;
        uint4* dz = reinterpret_cast<uint4*>(&g_dyn[0][0]);
        if (g < BATCH * CELLS / 16)
            dz[g] = make_uint4(0u, 0u, 0u, 0u);
    }
    __syncthreads();

    const int quads = NLI / 4;                    // 250000 quads per batch
    const int base  = b * quads;
    const size_t obase = (size_t)b * NLI;
    const int stride = bpb * blockDim.x;

    for (int q = blk * blockDim.x + threadIdx.x; q < quads; q += stride) {
        int t = base + q;

        int4 ca = coords4[2 * t];
        int4 cb = coords4[2 * t + 1];
        int4 ix = idx4[t];

        int f0 = ca.x * CANVAS + ca.y;
        int f1 = ca.z * CANVAS + ca.w;
        int f2 = cb.x * CANVAS + cb.y;
        int f3 = cb.z * CANVAS + cb.w;

        float d0 = (float)((sbits[f0 >> 5] >> (f0 & 31)) & 1u);
        float d1 = (float)((sbits[f1 >> 5] >> (f1 & 31)) & 1u);
        float d2 = (float)((sbits[f2 >> 5] >> (f2 & 31)) & 1u);
        float d3 = (float)((sbits[f3 >> 5] >> (f3 & 31)) & 1u);

        int local0 = 4 * q;
        if (ix.x == local0 && ix.y == local0 + 1 &&
            ix.z == local0 + 2 && ix.w == local0 + 3) {
            size_t o = obase + local0;
            *reinterpret_cast<float4*>(li_ind + o) =
                make_float4((float)f0, (float)f1, (float)f2, (float)f3);
            *reinterpret_cast<float4*>(li_dy + o) = make_float4(d0, d1, d2, d3);
        } else {
            li_ind[obase + ix.x] = (float)f0; li_dy[obase + ix.x] = d0;
            li_ind[obase + ix.y] = (float)f1; li_dy[obase + ix.y] = d1;
            li_ind[obase + ix.z] = (float)f2; li_dy[obase + ix.z] = d2;
            li_ind[obase + ix.w] = (float)f3; li_dy[obase + ix.w] = d3;
        }
    }
}

// ---------------------------------------------------------------------------
// Inputs (metadata order):
//   0: li_input       [B, NLI, 4]  f32   (UNUSED by reference)
//   1: li_coords      [B, NLI, 2]  i32
//   2: li_point_idxes [B, NLI]     i32
//   3: ra_input       [B, NRA, 5]  f32
//   4: ra_coords      [B, NRA, 2]  i32
//   5: ra_point_idxes [B, NRA]     i32
// Output: concat(li_dy[B,NLI], li_ind[B,NLI], ra_dy[B,NRA], ra_ind[B,NRA])
// ---------------------------------------------------------------------------
extern "C" void kernel_launch(void* const* d_in, const int* in_sizes, int n_in,
                              void* d_out, int out_size)
{
    const int4*   li_coords = (const int4*)  d_in[1];
    const int4*   li_idx    = (const int4*)  d_in[2];
    const float4* ra_in     = (const float4*)d_in[3];
    const int4*   ra_coords = (const int4*)  d_in[4];
    const int4*   ra_idx    = (const int4*)  d_in[5];

    float* out    = (float*)d_out;
    float* li_dy  = out;                               // [B*NLI]
    float* li_ind = out + (size_t)BATCH * NLI;         // [B*NLI]
    float* ra_dy  = out + (size_t)2 * BATCH * NLI;     // [B*NRA]
    float* ra_ind = ra_dy + (size_t)BATCH * NRA;       // [B*NRA]

    // 1) radar pass: 250K threads, 4 points each (g_dyn is zero on entry;
    //    zeroed at module load, then re-zeroed by li_kernel every call)
    ra_kernel_v4<<<(BATCH * NRA / 4 + 255) / 256, 256>>>(
        ra_coords, ra_in, ra_idx, ra_dy, ra_ind);

    // 2) separable byte-SIMD dilation -> bit-packed mask (32768 threads)
    dilate_kernel<<<BATCH * CANVAS * 32 / 256, 256>>>();

    // 3) lidar pass: 148 blocks/batch x 1024 threads, bit table in smem;
    //    also re-zeros g_dyn for the next call.
    li_kernel_smem<<<BATCH * 148, 1024>>>(li_coords, li_idx, li_dy, li_ind);
}

// round 11
// speedup vs baseline: 1.0083x; 1.0083x over previous
#include <cuda_runtime.h>

// Problem constants (match reference setup_inputs exactly)
#define CANVAS   512
#define CELLS    (CANVAS * CANVAS)   // 262144
#define BATCH    2
#define NLI      1000000
#define NRA      500000
#define NWORDS   (CELLS / 32)        // 8192 u32 words per batch bitmap

// Scratch: dyn byte table (scatter target) + dilated BIT table per batch.
// g_dyn is zero-initialized at module load; li_kernel re-zeros it at the end
// of every call (after dilate, its last reader), so every kernel_launch call
// -- correctness run and each graph replay -- sees it zeroed. No zero kernel.
__device__ unsigned char g_dyn[BATCH][CELLS];
__device__ unsigned int  g_nbits[BATCH][NWORDS];   // 32 KB per batch

// ---------------------------------------------------------------------------
// 1) Radar pass, 4 points/thread.
//    vr lives at v(5t+1).x, v(5t+2).y, v(5t+3).z, v(5t+4).w (skip first f4).
//    ra_dy positional; ra_ind scattered by idx (STG.128 fast path when the
//    4 idx values are contiguous-positional). dyn marks: racy byte stores.
// ---------------------------------------------------------------------------
__global__ void ra_kernel_v4(const int4*   __restrict__ coords4,  // [B*NRA/2]
                             const float4* __restrict__ in4,      // [B*NRA*5/4]
                             const int4*   __restrict__ idx4,     // [B*NRA/4]
                             float* __restrict__ ra_dy,           // [B*NRA]
                             float* __restrict__ ra_ind)          // [B*NRA]
{
    int t = blockIdx.x * blockDim.x + threadIdx.x;
    if (t >= BATCH * NRA / 4) return;
    int b = t / (NRA / 4);

    float4 v1 = in4[5 * t + 1];
    float4 v2 = in4[5 * t + 2];
    float4 v3 = in4[5 * t + 3];
    float4 v4 = in4[5 * t + 4];
    bool dy0 = fabsf(v1.x) > 0.1f;
    bool dy1 = fabsf(v2.y) > 0.1f;
    bool dy2 = fabsf(v3.z) > 0.1f;
    bool dy3 = fabsf(v4.w) > 0.1f;

    int4 ca = coords4[2 * t];
    int4 cb = coords4[2 * t + 1];
    int f0 = ca.x * CANVAS + ca.y;
    int f1 = ca.z * CANVAS + ca.w;
    int f2 = cb.x * CANVAS + cb.y;
    int f3 = cb.z * CANVAS + cb.w;

    reinterpret_cast<float4*>(ra_dy)[t] =
        make_float4(dy0 ? 1.f : 0.f, dy1 ? 1.f : 0.f,
                    dy2 ? 1.f : 0.f, dy3 ? 1.f : 0.f);

    int4 ix = idx4[t];
    int local0 = 4 * t - b * NRA;
    float* dst = ra_ind + (size_t)b * NRA;
    if (ix.x == local0 && ix.y == local0 + 1 &&
        ix.z == local0 + 2 && ix.w == local0 + 3) {
        *reinterpret_cast<float4*>(dst + local0) =
            make_float4((float)f0, (float)f1, (float)f2, (float)f3);
    } else {
        dst[ix.x] = (float)f0; dst[ix.y] = (float)f1;
        dst[ix.z] = (float)f2; dst[ix.w] = (float)f3;
    }

    unsigned char* dyn = g_dyn[b];
    if (dy0) dyn[f0] = 1;
    if (dy1) dyn[f1] = 1;
    if (dy2) dyn[f2] = 1;
    if (dy3) dyn[f3] = 1;
}

// ---------------------------------------------------------------------------
// 2) Separable 5x5 dilation in byte-SIMD, emitting a BIT-PACKED mask.
//    neigh[sy,sx] = OR_{i,j in [-2,2]} dyn[m(sy+i)][m(sx+j)], with the
//    reference's mod-513 wrap: m(-1)=m(512)=drop, m(-2)=511, m(513)=0.
//    One thread per (b, row, 16-byte segment) [lane == segment]; vertical OR
//    as uint4, horizontal spread via byte funnel-shifts, column-wrap fixups
//    (src col 511 -> out col 0, src col 0 -> out col 511). Bytes stay 0/1,
//    then get packed 4 bytes -> 4 bits; lane pairs merge 16+16 bits via shfl.
// ---------------------------------------------------------------------------
__global__ void dilate_kernel() {
    int t = blockIdx.x * blockDim.x + threadIdx.x;   // exactly 32768 threads
    int b  = t >> 14;            // 512 rows * 32 segs = 16384 per batch
    int rs = t & 16383;
    int sy = rs >> 5;
    int s  = rs & 31;            // 16-byte segment == lane id

    const unsigned char* dyn = g_dyn[b];
    const uint4* dyn4 = reinterpret_cast<const uint4*>(dyn);
    const unsigned int* dynw = reinterpret_cast<const unsigned int*>(dyn);

    unsigned int pw = 0, nw = 0;                  // boundary carry words
    unsigned int c0 = 0, c1 = 0, c2 = 0, c3 = 0;  // vertical OR of segment
    unsigned int vwrap = 0;                       // wrap byte (0/1)

    #pragma unroll
    for (int i = -2; i <= 2; i++) {
        int r = sy + i;
        if (r == -1 || r == 512) continue;        // phantom row -> dropped
        if (r == -2) r = 511;
        else if (r == 513) r = 0;
        int rb4 = r << 5;
        int rbw = r << 7;
        uint4 c = dyn4[rb4 + s];
        c0 |= c.x; c1 |= c.y; c2 |= c.z; c3 |= c.w;
        if (s > 0)  pw |= dynw[rbw + 4 * s - 1];
        if (s < 31) nw |= dynw[rbw + 4 * s + 4];
        if (s == 0)  vwrap |= dyn[(r << 9) + 511];   // src col 511
        if (s == 31) vwrap |= dyn[(r << 9) + 0];     // src col 0
    }

    unsigned int w0 = pw, w1 = c0, w2 = c1, w3 = c2, w4 = c3, w5 = nw;
    unsigned int r0 = w1 | __funnelshift_l(w0, w1, 8) | __funnelshift_l(w0, w1, 16)
                         | __funnelshift_r(w1, w2, 8) | __funnelshift_r(w1, w2, 16);
    unsigned int r1 = w2 | __funnelshift_l(w1, w2, 8) | __funnelshift_l(w1, w2, 16)
                         | __funnelshift_r(w2, w3, 8) | __funnelshift_r(w2, w3, 16);
    unsigned int r2 = w3 | __funnelshift_l(w2, w3, 8) | __funnelshift_l(w2, w3, 16)
                         | __funnelshift_r(w3, w4, 8) | __funnelshift_r(w3, w4, 16);
    unsigned int r3 = w4 | __funnelshift_l(w3, w4, 8) | __funnelshift_l(w3, w4, 16)
                         | __funnelshift_r(w4, w5, 8) | __funnelshift_r(w4, w5, 16);

    if (s == 0)  r0 |= vwrap;         // out col 0   <- src col 511
    if (s == 31) r3 |= vwrap << 24;   // out col 511 <- src col 0

    // pack 16 bytes (each exactly 0/1) -> 16 bits; bit k = col 16*s + k
    unsigned int nib0 = (r0 | (r0 >> 7) | (r0 >> 14) | (r0 >> 21)) & 0xF;
    unsigned int nib1 = (r1 | (r1 >> 7) | (r1 >> 14) | (r1 >> 21)) & 0xF;
    unsigned int nib2 = (r2 | (r2 >> 7) | (r2 >> 14) | (r2 >> 21)) & 0xF;
    unsigned int nib3 = (r3 | (r3 >> 7) | (r3 >> 14) | (r3 >> 21)) & 0xF;
    unsigned int bits16 = nib0 | (nib1 << 4) | (nib2 << 8) | (nib3 << 12);

    // lane pairs (2k, 2k+1) -> one u32 word covering cols 32k..32k+31
    unsigned int hi = __shfl_down_sync(0xFFFFFFFFu, bits16, 1);
    if ((s & 1) == 0)
        g_nbits[b][(sy << 4) + (s >> 1)] = bits16 | (hi << 16);
}

// ---------------------------------------------------------------------------
// 3) Lidar pass, 1024 threads/block, 2 blocks/SM (100% occupancy).
//    148 blocks per batch; each block loads the 32 KB bit table into smem
//    once, strides over point-quads (coalesced LDG.128 in, random LDS bit
//    test, STG.128 out), then helps re-zero g_dyn for the next call.
// ---------------------------------------------------------------------------
__global__ void __launch_bounds__(1024, 2)
li_kernel_smem(const int4* __restrict__ coords4,  // [B*NLI/2]
               const int4* __restrict__ idx4,     // [B*NLI/4]
               float* __restrict__ li_dy,         // [B*NLI]
               float* __restrict__ li_ind)        // [B*NLI]
{
    __shared__ unsigned int sbits[NWORDS];        // 32 KB

    int bpb = gridDim.x / BATCH;                  // blocks per batch (148)
    int b   = blockIdx.x / bpb;
    int blk = blockIdx.x - b * bpb;

    // cooperative load of this batch's bit table (2048 uint4)
    const uint4* src = reinterpret_cast<const uint4*>(g_nbits[b]);
    uint4* dstv = reinterpret_cast<uint4*>(sbits);
    for (int i = threadIdx.x; i < NWORDS / 4; i += blockDim.x)
        dstv[i] = src[i];

    // re-zero g_dyn (dilate was its last reader; restores the entry
    // invariant for the next kernel_launch call). 32768 uint4 total.
    {
        int g = blockIdx.x * blockDim.x + threadIdx.x;
        uint4* dz = reinterpret_cast<uint4*>(&g_dyn[0][0]);
        if (g < BATCH * CELLS / 16)
            dz[g] = make_uint4(0u, 0u, 0u, 0u);
    }
    __syncthreads();

    const int quads = NLI / 4;                    // 250000 quads per batch
    const int base  = b * quads;
    const size_t obase = (size_t)b * NLI;
    const int stride = bpb * blockDim.x;

    for (int q = blk * blockDim.x + threadIdx.x; q < quads; q += stride) {
        int t = base + q;

        int4 ca = coords4[2 * t];
        int4 cb = coords4[2 * t + 1];
        int4 ix = idx4[t];

        int f0 = ca.x * CANVAS + ca.y;
        int f1 = ca.z * CANVAS + ca.w;
        int f2 = cb.x * CANVAS + cb.y;
        int f3 = cb.z * CANVAS + cb.w;

        float d0 = (float)((sbits[f0 >> 5] >> (f0 & 31)) & 1u);
        float d1 = (float)((sbits[f1 >> 5] >> (f1 & 31)) & 1u);
        float d2 = (float)((sbits[f2 >> 5] >> (f2 & 31)) & 1u);
        float d3 = (float)((sbits[f3 >> 5] >> (f3 & 31)) & 1u);

        int local0 = 4 * q;
        if (ix.x == local0 && ix.y == local0 + 1 &&
            ix.z == local0 + 2 && ix.w == local0 + 3) {
            size_t o = obase + local0;
            *reinterpret_cast<float4*>(li_ind + o) =
                make_float4((float)f0, (float)f1, (float)f2, (float)f3);
            *reinterpret_cast<float4*>(li_dy + o) = make_float4(d0, d1, d2, d3);
        } else {
            li_ind[obase + ix.x] = (float)f0; li_dy[obase + ix.x] = d0;
            li_ind[obase + ix.y] = (float)f1; li_dy[obase + ix.y] = d1;
            li_ind[obase + ix.z] = (float)f2; li_dy[obase + ix.z] = d2;
            li_ind[obase + ix.w] = (float)f3; li_dy[obase + ix.w] = d3;
        }
    }
}

// ---------------------------------------------------------------------------
// Inputs (metadata order):
//   0: li_input       [B, NLI, 4]  f32   (UNUSED by reference)
//   1: li_coords      [B, NLI, 2]  i32
//   2: li_point_idxes [B, NLI]     i32
//   3: ra_input       [B, NRA, 5]  f32
//   4: ra_coords      [B, NRA, 2]  i32
//   5: ra_point_idxes [B, NRA]     i32
// Output: concat(li_dy[B,NLI], li_ind[B,NLI], ra_dy[B,NRA], ra_ind[B,NRA])
// ---------------------------------------------------------------------------
extern "C" void kernel_launch(void* const* d_in, const int* in_sizes, int n_in,
                              void* d_out, int out_size)
{
    const int4*   li_coords = (const int4*)  d_in[1];
    const int4*   li_idx    = (const int4*)  d_in[2];
    const float4* ra_in     = (const float4*)d_in[3];
    const int4*   ra_coords = (const int4*)  d_in[4];
    const int4*   ra_idx    = (const int4*)  d_in[5];

    float* out    = (float*)d_out;
    float* li_dy  = out;                               // [B*NLI]
    float* li_ind = out + (size_t)BATCH * NLI;         // [B*NLI]
    float* ra_dy  = out + (size_t)2 * BATCH * NLI;     // [B*NRA]
    float* ra_ind = ra_dy + (size_t)BATCH * NRA;       // [B*NRA]

    // 1) radar pass: 250K threads, 4 points each (g_dyn is zero on entry;
    //    zeroed at module load, then re-zeroed by li_kernel every call)
    ra_kernel_v4<<<(BATCH * NRA / 4 + 255) / 256, 256>>>(
        ra_coords, ra_in, ra_idx, ra_dy, ra_ind);

    // 2) separable byte-SIMD dilation -> bit-packed mask (32768 threads)
    dilate_kernel<<<BATCH * CANVAS * 32 / 256, 256>>>();

    // 3) lidar pass: 148 blocks/batch x 1024 threads, bit table in smem;
    //    also re-zeros g_dyn for the next call.
    li_kernel_smem<<<BATCH * 148, 1024>>>(li_coords, li_idx, li_dy, li_ind);
}

// round 12
// speedup vs baseline: 1.0094x; 1.0012x over previous
#include <cuda_runtime.h>

// Problem constants (match reference setup_inputs exactly)
#define CANVAS   512
#define CELLS    (CANVAS * CANVAS)   // 262144
#define BATCH    2
#define NLI      1000000
#define NRA      500000
#define NWORDS   (CELLS / 32)        // 8192 u32 words per batch bitmap

// Scratch: dyn byte table (scatter target) + dilated BIT table per batch.
// g_dyn is zero-initialized at module load; li_kernel re-zeros it at the end
// of every call (after dilate, its last reader), so every kernel_launch call
// -- correctness run and each graph replay -- sees it zeroed. No zero kernel.
__device__ unsigned char g_dyn[BATCH][CELLS];
__device__ unsigned int  g_nbits[BATCH][NWORDS];   // 32 KB per batch

// ---------------------------------------------------------------------------
// 1) Radar pass, 4 points/thread.
//    vr lives at v(5t+1).x, v(5t+2).y, v(5t+3).z, v(5t+4).w (skip first f4).
//    ra_dy positional; ra_ind scattered by idx (STG.128 fast path when the
//    4 idx values are contiguous-positional). dyn marks: racy byte stores.
// ---------------------------------------------------------------------------
__global__ void ra_kernel_v4(const int4*   __restrict__ coords4,  // [B*NRA/2]
                             const float4* __restrict__ in4,      // [B*NRA*5/4]
                             const int4*   __restrict__ idx4,     // [B*NRA/4]
                             float* __restrict__ ra_dy,           // [B*NRA]
                             float* __restrict__ ra_ind)          // [B*NRA]
{
    int t = blockIdx.x * blockDim.x + threadIdx.x;
    if (t >= BATCH * NRA / 4) return;
    int b = t / (NRA / 4);

    float4 v1 = in4[5 * t + 1];
    float4 v2 = in4[5 * t + 2];
    float4 v3 = in4[5 * t + 3];
    float4 v4 = in4[5 * t + 4];
    bool dy0 = fabsf(v1.x) > 0.1f;
    bool dy1 = fabsf(v2.y) > 0.1f;
    bool dy2 = fabsf(v3.z) > 0.1f;
    bool dy3 = fabsf(v4.w) > 0.1f;

    int4 ca = coords4[2 * t];
    int4 cb = coords4[2 * t + 1];
    int f0 = ca.x * CANVAS + ca.y;
    int f1 = ca.z * CANVAS + ca.w;
    int f2 = cb.x * CANVAS + cb.y;
    int f3 = cb.z * CANVAS + cb.w;

    reinterpret_cast<float4*>(ra_dy)[t] =
        make_float4(dy0 ? 1.f : 0.f, dy1 ? 1.f : 0.f,
                    dy2 ? 1.f : 0.f, dy3 ? 1.f : 0.f);

    int4 ix = idx4[t];
    int local0 = 4 * t - b * NRA;
    float* dst = ra_ind + (size_t)b * NRA;
    if (ix.x == local0 && ix.y == local0 + 1 &&
        ix.z == local0 + 2 && ix.w == local0 + 3) {
        *reinterpret_cast<float4*>(dst + local0) =
            make_float4((float)f0, (float)f1, (float)f2, (float)f3);
    } else {
        dst[ix.x] = (float)f0; dst[ix.y] = (float)f1;
        dst[ix.z] = (float)f2; dst[ix.w] = (float)f3;
    }

    unsigned char* dyn = g_dyn[b];
    if (dy0) dyn[f0] = 1;
    if (dy1) dyn[f1] = 1;
    if (dy2) dyn[f2] = 1;
    if (dy3) dyn[f3] = 1;
}

// ---------------------------------------------------------------------------
// 2) Separable 5x5 dilation in byte-SIMD, emitting a BIT-PACKED mask.
//    neigh[sy,sx] = OR_{i,j in [-2,2]} dyn[m(sy+i)][m(sx+j)], with the
//    reference's mod-513 wrap: m(-1)=m(512)=drop, m(-2)=511, m(513)=0.
//    One thread per (b, row, 16-byte segment) [lane == segment]; vertical OR
//    as uint4, horizontal spread via byte funnel-shifts, column-wrap fixups
//    (src col 511 -> out col 0, src col 0 -> out col 511). Bytes stay 0/1,
//    then get packed 4 bytes -> 4 bits; lane pairs merge 16+16 bits via shfl.
// ---------------------------------------------------------------------------
__global__ void dilate_kernel() {
    int t = blockIdx.x * blockDim.x + threadIdx.x;   // exactly 32768 threads
    int b  = t >> 14;            // 512 rows * 32 segs = 16384 per batch
    int rs = t & 16383;
    int sy = rs >> 5;
    int s  = rs & 31;            // 16-byte segment == lane id

    const unsigned char* dyn = g_dyn[b];
    const uint4* dyn4 = reinterpret_cast<const uint4*>(dyn);
    const unsigned int* dynw = reinterpret_cast<const unsigned int*>(dyn);

    unsigned int pw = 0, nw = 0;                  // boundary carry words
    unsigned int c0 = 0, c1 = 0, c2 = 0, c3 = 0;  // vertical OR of segment
    unsigned int vwrap = 0;                       // wrap byte (0/1)

    #pragma unroll
    for (int i = -2; i <= 2; i++) {
        int r = sy + i;
        if (r == -1 || r == 512) continue;        // phantom row -> dropped
        if (r == -2) r = 511;
        else if (r == 513) r = 0;
        int rb4 = r << 5;
        int rbw = r << 7;
        uint4 c = dyn4[rb4 + s];
        c0 |= c.x; c1 |= c.y; c2 |= c.z; c3 |= c.w;
        if (s > 0)  pw |= dynw[rbw + 4 * s - 1];
        if (s < 31) nw |= dynw[rbw + 4 * s + 4];
        if (s == 0)  vwrap |= dyn[(r << 9) + 511];   // src col 511
        if (s == 31) vwrap |= dyn[(r << 9) + 0];     // src col 0
    }

    unsigned int w0 = pw, w1 = c0, w2 = c1, w3 = c2, w4 = c3, w5 = nw;
    unsigned int r0 = w1 | __funnelshift_l(w0, w1, 8) | __funnelshift_l(w0, w1, 16)
                         | __funnelshift_r(w1, w2, 8) | __funnelshift_r(w1, w2, 16);
    unsigned int r1 = w2 | __funnelshift_l(w1, w2, 8) | __funnelshift_l(w1, w2, 16)
                         | __funnelshift_r(w2, w3, 8) | __funnelshift_r(w2, w3, 16);
    unsigned int r2 = w3 | __funnelshift_l(w2, w3, 8) | __funnelshift_l(w2, w3, 16)
                         | __funnelshift_r(w3, w4, 8) | __funnelshift_r(w3, w4, 16);
    unsigned int r3 = w4 | __funnelshift_l(w3, w4, 8) | __funnelshift_l(w3, w4, 16)
                         | __funnelshift_r(w4, w5, 8) | __funnelshift_r(w4, w5, 16);

    if (s == 0)  r0 |= vwrap;         // out col 0   <- src col 511
    if (s == 31) r3 |= vwrap << 24;   // out col 511 <- src col 0

    // pack 16 bytes (each exactly 0/1) -> 16 bits; bit k = col 16*s + k
    unsigned int nib0 = (r0 | (r0 >> 7) | (r0 >> 14) | (r0 >> 21)) & 0xF;
    unsigned int nib1 = (r1 | (r1 >> 7) | (r1 >> 14) | (r1 >> 21)) & 0xF;
    unsigned int nib2 = (r2 | (r2 >> 7) | (r2 >> 14) | (r2 >> 21)) & 0xF;
    unsigned int nib3 = (r3 | (r3 >> 7) | (r3 >> 14) | (r3 >> 21)) & 0xF;
    unsigned int bits16 = nib0 | (nib1 << 4) | (nib2 << 8) | (nib3 << 12);

    // lane pairs (2k, 2k+1) -> one u32 word covering cols 32k..32k+31
    unsigned int hi = __shfl_down_sync(0xFFFFFFFFu, bits16, 1);
    if ((s & 1) == 0)
        g_nbits[b][(sy << 4) + (s >> 1)] = bits16 | (hi << 16);
}

// ---------------------------------------------------------------------------
// 3) Lidar pass, 1024 threads/block, 2 blocks/SM (100% occupancy).
//    148 blocks per batch; each block loads the 32 KB bit table into smem
//    once, strides over point-quads (coalesced LDG.128 in, random LDS bit
//    test, STG.128 out), then helps re-zero g_dyn for the next call.
// ---------------------------------------------------------------------------
__global__ void __launch_bounds__(1024, 2)
li_kernel_smem(const int4* __restrict__ coords4,  // [B*NLI/2]
               const int4* __restrict__ idx4,     // [B*NLI/4]
               float* __restrict__ li_dy,         // [B*NLI]
               float* __restrict__ li_ind)        // [B*NLI]
{
    __shared__ unsigned int sbits[NWORDS];        // 32 KB

    int bpb = gridDim.x / BATCH;                  // blocks per batch (148)
    int b   = blockIdx.x / bpb;
    int blk = blockIdx.x - b * bpb;

    // cooperative load of this batch's bit table (2048 uint4)
    const uint4* src = reinterpret_cast<const uint4*>(g_nbits[b]);
    uint4* dstv = reinterpret_cast<uint4*>(sbits);
    for (int i = threadIdx.x; i < NWORDS / 4; i += blockDim.x)
        dstv[i] = src[i];

    // re-zero g_dyn (dilate was its last reader; restores the entry
    // invariant for the next kernel_launch call). 32768 uint4 total.
    {
        int g = blockIdx.x * blockDim.x + threadIdx.x;
        uint4* dz = reinterpret_cast<uint4*>(&g_dyn[0][0]);
        if (g < BATCH * CELLS / 16)
            dz[g] = make_uint4(0u, 0u, 0u, 0u);
    }
    __syncthreads();

    const int quads = NLI / 4;                    // 250000 quads per batch
    const int base  = b * quads;
    const size_t obase = (size_t)b * NLI;
    const int stride = bpb * blockDim.x;

    for (int q = blk * blockDim.x + threadIdx.x; q < quads; q += stride) {
        int t = base + q;

        int4 ca = coords4[2 * t];
        int4 cb = coords4[2 * t + 1];
        int4 ix = idx4[t];

        int f0 = ca.x * CANVAS + ca.y;
        int f1 = ca.z * CANVAS + ca.w;
        int f2 = cb.x * CANVAS + cb.y;
        int f3 = cb.z * CANVAS + cb.w;

        float d0 = (float)((sbits[f0 >> 5] >> (f0 & 31)) & 1u);
        float d1 = (float)((sbits[f1 >> 5] >> (f1 & 31)) & 1u);
        float d2 = (float)((sbits[f2 >> 5] >> (f2 & 31)) & 1u);
        float d3 = (float)((sbits[f3 >> 5] >> (f3 & 31)) & 1u);

        int local0 = 4 * q;
        if (ix.x == local0 && ix.y == local0 + 1 &&
            ix.z == local0 + 2 && ix.w == local0 + 3) {
            size_t o = obase + local0;
            *reinterpret_cast<float4*>(li_ind + o) =
                make_float4((float)f0, (float)f1, (float)f2, (float)f3);
            *reinterpret_cast<float4*>(li_dy + o) = make_float4(d0, d1, d2, d3);
        } else {
            li_ind[obase + ix.x] = (float)f0; li_dy[obase + ix.x] = d0;
            li_ind[obase + ix.y] = (float)f1; li_dy[obase + ix.y] = d1;
            li_ind[obase + ix.z] = (float)f2; li_dy[obase + ix.z] = d2;
            li_ind[obase + ix.w] = (float)f3; li_dy[obase + ix.w] = d3;
        }
    }
}

// ---------------------------------------------------------------------------
// Inputs (metadata order):
//   0: li_input       [B, NLI, 4]  f32   (UNUSED by reference)
//   1: li_coords      [B, NLI, 2]  i32
//   2: li_point_idxes [B, NLI]     i32
//   3: ra_input       [B, NRA, 5]  f32
//   4: ra_coords      [B, NRA, 2]  i32
//   5: ra_point_idxes [B, NRA]     i32
// Output: concat(li_dy[B,NLI], li_ind[B,NLI], ra_dy[B,NRA], ra_ind[B,NRA])
// ---------------------------------------------------------------------------
extern "C" void kernel_launch(void* const* d_in, const int* in_sizes, int n_in,
                              void* d_out, int out_size)
{
    const int4*   li_coords = (const int4*)  d_in[1];
    const int4*   li_idx    = (const int4*)  d_in[2];
    const float4* ra_in     = (const float4*)d_in[3];
    const int4*   ra_coords = (const int4*)  d_in[4];
    const int4*   ra_idx    = (const int4*)  d_in[5];

    float* out    = (float*)d_out;
    float* li_dy  = out;                               // [B*NLI]
    float* li_ind = out + (size_t)BATCH * NLI;         // [B*NLI]
    float* ra_dy  = out + (size_t)2 * BATCH * NLI;     // [B*NRA]
    float* ra_ind = ra_dy + (size_t)BATCH * NRA;       // [B*NRA]

    // 1) radar pass: 250K threads, 4 points each (g_dyn is zero on entry;
    //    zeroed at module load, then re-zeroed by li_kernel every call)
    ra_kernel_v4<<<(BATCH * NRA / 4 + 255) / 256, 256>>>(
        ra_coords, ra_in, ra_idx, ra_dy, ra_ind);

    // 2) separable byte-SIMD dilation -> bit-packed mask (32768 threads)
    dilate_kernel<<<BATCH * CANVAS * 32 / 256, 256>>>();

    // 3) lidar pass: 148 blocks/batch x 1024 threads, bit table in smem;
    //    also re-zeros g_dyn for the next call.
    li_kernel_smem<<<BATCH * 148, 1024>>>(li_coords, li_idx, li_dy, li_ind);
}